// round 4
// baseline (speedup 1.0000x reference)
#include <cuda_runtime.h>
#include <math.h>

#define NROWS   12800     // B*C
#define BATCH   256
#define CDIM    50
#define INPUT   128
#define INTER   64
#define HIDDEN  128
#define NSLOT   11
#define USTRIDE (NSLOT * INTER)   // 704
#define NCHUNK  13
#define NB      (NSLOT * NCHUNK)  // 143 CTAs, <= 148 SMs -> co-resident
#define RPC     985               // ceil(12800/13)
#define UVEC4   (BATCH * USTRIDE / 4)  // 45056 float4

// Bucketed accumulator: u[b][dist_slot][j], fp32. 720 KB static device scratch.
__device__ float g_u[BATCH * USTRIDE];
// Monotonic barrier counters (NEVER reset; safe across graph replays).
__device__ unsigned g_ctr[2];

__device__ __forceinline__ void grid_bar(int id) {
    __syncthreads();
    if (threadIdx.x == 0) {
        __threadfence();
        unsigned r = atomicAdd(&g_ctr[id], 1u);
        unsigned target = (r / NB + 1u) * NB;
        while (*(volatile unsigned*)&g_ctr[id] < target) { }
        __threadfence();
    }
    __syncthreads();
}

__global__ __launch_bounds__(256) void fused_kernel(
    const float* __restrict__ x,     // (B,C,INPUT)
    const int* __restrict__ tc,      // (B,C)
    const int* __restrict__ dc,      // (B,C)
    const int* __restrict__ mask,    // (B,C) bool->int32
    const float* __restrict__ h,     // (B,HIDDEN)
    const float* __restrict__ tw,    // (NSLOT,INPUT,INTER)
    const float* __restrict__ dw,    // (NSLOT,INTER,HIDDEN)
    const float* __restrict__ hw,    // (HIDDEN,HIDDEN)
    float* __restrict__ out)         // (B,HIDDEN)
{
    __shared__ union {
        struct {                       // phase 1
            float tws[INPUT * INTER];  // 32 KB
            int   list[RPC + 1];
            int   cnt;
        } s1;
        struct {                       // phase 2
            float ws[INTER * HIDDEN];  // 32 KB
            float us[4 * INTER];
            float hs[4 * HIDDEN];
        } s2;
    } sh;

    const int cta = blockIdx.x;
    const int tid = threadIdx.x;

    // ---- Phase 0: zero the accumulator -----------------------------------
    for (int i = cta * 256 + tid; i < UVEC4; i += NB * 256)
        ((float4*)g_u)[i] = make_float4(0.f, 0.f, 0.f, 0.f);

    // ---- Phase 1: slot-major x@tw with compaction + 2-row pairing --------
    const int s     = cta / NCHUNK;       // 0..10
    const int chunk = cta % NCHUNK;       // 0..12
    const int rbeg  = chunk * RPC;
    const int rend  = (rbeg + RPC < NROWS) ? rbeg + RPC : NROWS;

    if (tid == 0) sh.s1.cnt = 0;
    {   // load tw[s] into smem (overlaps with other CTAs' zero phase; no
        // dependency on g_u, so safe before the barrier)
        const float4* src = (const float4*)(tw + (size_t)s * INPUT * INTER);
        #pragma unroll 4
        for (int i = tid; i < (INPUT * INTER) / 4; i += 256)
            ((float4*)sh.s1.tws)[i] = src[i];
    }
    grid_bar(0);   // also orders cnt=0 and tws for this CTA

    // coalesced scan + compaction
    for (int i = rbeg + tid; i < rend; i += 256) {
        if (tc[i] == s && mask[i] != 0) {
            int pos = atomicAdd(&sh.s1.cnt, 1);
            sh.s1.list[pos] = (dc[i] << 16) | i;
        }
    }
    __syncthreads();

    const int n    = sh.s1.cnt;
    const int warp = tid >> 5;
    const int lane = tid & 31;
    const int j0   = lane * 2;

    for (int i = warp * 2; i < n; i += 16) {
        const int  e0   = sh.s1.list[i];
        const bool has2 = (i + 1) < n;
        const int  e1   = has2 ? sh.s1.list[i + 1] : e0;
        const int  ra   = e0 & 0xFFFF, da = e0 >> 16;
        const int  rb   = e1 & 0xFFFF, db = e1 >> 16;
        const float* xa = x + (size_t)ra * INPUT;
        const float* xb = x + (size_t)rb * INPUT;

        float a0 = 0.f, a1 = 0.f, b0 = 0.f, b1 = 0.f;
        #pragma unroll 8
        for (int k = 0; k < INPUT; k += 4) {
            float4 va = *(const float4*)(xa + k);   // broadcast across warp
            float4 vb = *(const float4*)(xb + k);
            float2 w0 = *(const float2*)(sh.s1.tws + (k + 0) * INTER + j0);
            float2 w1 = *(const float2*)(sh.s1.tws + (k + 1) * INTER + j0);
            float2 w2 = *(const float2*)(sh.s1.tws + (k + 2) * INTER + j0);
            float2 w3 = *(const float2*)(sh.s1.tws + (k + 3) * INTER + j0);
            a0 = fmaf(va.x, w0.x, a0);  a1 = fmaf(va.x, w0.y, a1);
            b0 = fmaf(vb.x, w0.x, b0);  b1 = fmaf(vb.x, w0.y, b1);
            a0 = fmaf(va.y, w1.x, a0);  a1 = fmaf(va.y, w1.y, a1);
            b0 = fmaf(vb.y, w1.x, b0);  b1 = fmaf(vb.y, w1.y, b1);
            a0 = fmaf(va.z, w2.x, a0);  a1 = fmaf(va.z, w2.y, a1);
            b0 = fmaf(vb.z, w2.x, b0);  b1 = fmaf(vb.z, w2.y, b1);
            a0 = fmaf(va.w, w3.x, a0);  a1 = fmaf(va.w, w3.y, a1);
            b0 = fmaf(vb.w, w3.x, b0);  b1 = fmaf(vb.w, w3.y, b1);
        }

        float* ua = g_u + (size_t)(ra / CDIM) * USTRIDE + da * INTER + j0;
        atomicAdd(ua,     a0);
        atomicAdd(ua + 1, a1);
        if (has2) {
            float* ub = g_u + (size_t)(rb / CDIM) * USTRIDE + db * INTER + j0;
            atomicAdd(ub,     b0);
            atomicAdd(ub + 1, b1);
        }
    }

    grid_bar(1);

    // ---- Phase 2: dense u@dw + h@Hw + sigmoid (first 64 CTAs) ------------
    if (cta >= 64) return;

    const int bbase = cta * 4;
    const int b0i   = tid >> 7;     // 0..1
    const int hid   = tid & 127;

    for (int i = tid; i < 4 * HIDDEN; i += 256)
        sh.s2.hs[i] = h[(size_t)bbase * HIDDEN + i];

    float acc0 = 0.f, acc1 = 0.f;

    for (int d = 0; d < NSLOT; d++) {
        __syncthreads();
        sh.s2.us[tid] =
            g_u[(size_t)(bbase + (tid >> 6)) * USTRIDE + d * INTER + (tid & 63)];
        {
            const float4* src = (const float4*)(dw + (size_t)d * INTER * HIDDEN);
            #pragma unroll 4
            for (int i = tid; i < (INTER * HIDDEN) / 4; i += 256)
                ((float4*)sh.s2.ws)[i] = src[i];
        }
        __syncthreads();
        #pragma unroll
        for (int j = 0; j < INTER; j++) {
            float w = sh.s2.ws[j * HIDDEN + hid];
            acc0 = fmaf(sh.s2.us[b0i * INTER + j],       w, acc0);
            acc1 = fmaf(sh.s2.us[(b0i + 2) * INTER + j], w, acc1);
        }
    }

    for (int half = 0; half < 2; half++) {
        __syncthreads();
        {
            const float4* src = (const float4*)(hw + (size_t)half * 64 * HIDDEN);
            #pragma unroll 4
            for (int i = tid; i < (64 * HIDDEN) / 4; i += 256)
                ((float4*)sh.s2.ws)[i] = src[i];
        }
        __syncthreads();
        #pragma unroll
        for (int j = 0; j < 64; j++) {
            float w = sh.s2.ws[j * HIDDEN + hid];
            int k = half * 64 + j;
            acc0 = fmaf(sh.s2.hs[b0i * HIDDEN + k],       w, acc0);
            acc1 = fmaf(sh.s2.hs[(b0i + 2) * HIDDEN + k], w, acc1);
        }
    }

    out[(size_t)(bbase + b0i)     * HIDDEN + hid] = 1.f / (1.f + expf(-acc0));
    out[(size_t)(bbase + b0i + 2) * HIDDEN + hid] = 1.f / (1.f + expf(-acc1));
}

extern "C" void kernel_launch(void* const* d_in, const int* in_sizes, int n_in,
                              void* d_out, int out_size) {
    const float* x    = (const float*)d_in[0];
    const int*   tc   = (const int*)d_in[1];
    const int*   dc   = (const int*)d_in[2];
    const int*   mask = (const int*)d_in[3];
    const float* h    = (const float*)d_in[4];
    const float* tw   = (const float*)d_in[5];
    const float* dw   = (const float*)d_in[6];
    const float* hw   = (const float*)d_in[7];
    float*       out  = (float*)d_out;

    fused_kernel<<<NB, 256>>>(x, tc, dc, mask, h, tw, dw, hw, out);
}

// round 5
// speedup vs baseline: 1.5253x; 1.5253x over previous
#include <cuda_runtime.h>
#include <math.h>

#define NROWS   12800     // B*C
#define BATCH   256
#define CDIM    50
#define INPUT   128
#define INTER   64
#define HIDDEN  128
#define NSLOT   11
#define USTRIDE (NSLOT * INTER)   // 704
#define GRIDY   64
#define RPC     (NROWS / GRIDY)   // 200 rows per chunk

// Bucketed accumulator u[b][dist_slot][j], fp32. Zero-initialized at module
// load; stage2 re-zeroes it after consuming, so every launch (and every graph
// replay) starts from zeros without a dedicated zeroing kernel.
__device__ float g_u[BATCH * USTRIDE];

// ---------------------------------------------------------------------------
// K1: slot-major stage 1 with in-CTA compaction + 2-row pairing.
// grid = (11 slots, 64 row-chunks) = 704 CTAs -> ~5 CTAs/SM co-resident.
// ---------------------------------------------------------------------------
__global__ __launch_bounds__(256) void stage1_kernel(
    const float* __restrict__ x,          // (B,C,INPUT)
    const int* __restrict__ tc,           // (B,C)
    const int* __restrict__ dc,           // (B,C)
    const int* __restrict__ mask,         // (B,C) bool promoted to int32
    const float* __restrict__ tw)         // (NSLOT, INPUT, INTER)
{
    __shared__ float tws[INPUT * INTER];  // 32 KB
    __shared__ int   list[RPC];           // (dc<<16)|row
    __shared__ int   cnt;

    const int s  = blockIdx.x;
    const int r0 = blockIdx.y * RPC;
    const int tid = threadIdx.x;

    if (tid == 0) cnt = 0;

    {   // cooperative smem load of tw[s]
        const float4* src = (const float4*)(tw + (size_t)s * INPUT * INTER);
        #pragma unroll 4
        for (int i = tid; i < (INPUT * INTER) / 4; i += 256)
            ((float4*)tws)[i] = src[i];
    }
    __syncthreads();

    // Phase A: coalesced scan + compaction (one pass, <=200 rows)
    if (tid < RPC) {
        int r = r0 + tid;
        if (tc[r] == s && mask[r] != 0) {
            int pos = atomicAdd(&cnt, 1);
            list[pos] = (dc[r] << 16) | r;
        }
    }
    __syncthreads();

    const int n    = cnt;
    const int warp = tid >> 5;
    const int lane = tid & 31;
    const int j0   = lane * 2;

    // Phase B: paired rows share one weight read
    for (int i = warp * 2; i < n; i += 16) {
        const int  e0   = list[i];
        const bool has2 = (i + 1) < n;
        const int  e1   = has2 ? list[i + 1] : e0;
        const int  ra   = e0 & 0xFFFF, da = e0 >> 16;
        const int  rb   = e1 & 0xFFFF, db = e1 >> 16;
        const float* xa = x + (size_t)ra * INPUT;
        const float* xb = x + (size_t)rb * INPUT;

        float a0 = 0.f, a1 = 0.f, b0 = 0.f, b1 = 0.f;
        #pragma unroll 8
        for (int k = 0; k < INPUT; k += 4) {
            float4 va = *(const float4*)(xa + k);   // broadcast across warp
            float4 vb = *(const float4*)(xb + k);
            float2 w0 = *(const float2*)(tws + (k + 0) * INTER + j0);
            float2 w1 = *(const float2*)(tws + (k + 1) * INTER + j0);
            float2 w2 = *(const float2*)(tws + (k + 2) * INTER + j0);
            float2 w3 = *(const float2*)(tws + (k + 3) * INTER + j0);
            a0 = fmaf(va.x, w0.x, a0);  a1 = fmaf(va.x, w0.y, a1);
            b0 = fmaf(vb.x, w0.x, b0);  b1 = fmaf(vb.x, w0.y, b1);
            a0 = fmaf(va.y, w1.x, a0);  a1 = fmaf(va.y, w1.y, a1);
            b0 = fmaf(vb.y, w1.x, b0);  b1 = fmaf(vb.y, w1.y, b1);
            a0 = fmaf(va.z, w2.x, a0);  a1 = fmaf(va.z, w2.y, a1);
            b0 = fmaf(vb.z, w2.x, b0);  b1 = fmaf(vb.z, w2.y, b1);
            a0 = fmaf(va.w, w3.x, a0);  a1 = fmaf(va.w, w3.y, a1);
            b0 = fmaf(vb.w, w3.x, b0);  b1 = fmaf(vb.w, w3.y, b1);
        }

        float* ua = g_u + (size_t)(ra / CDIM) * USTRIDE + da * INTER + j0;
        atomicAdd(ua,     a0);
        atomicAdd(ua + 1, a1);
        if (has2) {
            float* ub = g_u + (size_t)(rb / CDIM) * USTRIDE + db * INTER + j0;
            atomicAdd(ub,     b0);
            atomicAdd(ub + 1, b1);
        }
    }
}

// ---------------------------------------------------------------------------
// K2: dense stage 2 + hidden path + sigmoid, with read-then-rezero of g_u.
// grid.x = 64 CTAs, 4 batches each, 256 threads -> 2 outputs per thread.
// u for all 4 batches is hoisted into smem up front.
// ---------------------------------------------------------------------------
__global__ __launch_bounds__(256) void stage2_kernel(
    const float* __restrict__ h,    // (B, HIDDEN)
    const float* __restrict__ dw,   // (NSLOT, INTER, HIDDEN)
    const float* __restrict__ hw,   // (HIDDEN, HIDDEN)
    float* __restrict__ out)        // (B, HIDDEN)
{
    __shared__ float ws[INTER * HIDDEN];   // 32 KB, reused for Hw halves
    __shared__ float us[4 * USTRIDE];      // 11.3 KB: u for 4 batches
    __shared__ float hs[4 * HIDDEN];       // 2 KB

    const int t = threadIdx.x;
    const int bbase = blockIdx.x * 4;
    const int b0  = t >> 7;     // 0..1
    const int hid = t & 127;

    // Load u slice into smem AND re-zero g_u for the next launch/replay.
    // Each element is touched by exactly one thread -> no race.
    {
        float4* gu4 = (float4*)(g_u + (size_t)bbase * USTRIDE);
        float4* us4 = (float4*)us;
        const float4 z = make_float4(0.f, 0.f, 0.f, 0.f);
        #pragma unroll
        for (int i = t; i < 4 * USTRIDE / 4; i += 256) {
            float4 v = gu4[i];
            us4[i] = v;
            gu4[i] = z;
        }
    }
    for (int i = t; i < 4 * HIDDEN; i += 256)
        hs[i] = h[(size_t)bbase * HIDDEN + i];

    float acc0 = 0.f, acc1 = 0.f;

    for (int d = 0; d < NSLOT; d++) {
        {
            const float4* src = (const float4*)(dw + (size_t)d * INTER * HIDDEN);
            #pragma unroll 4
            for (int i = t; i < (INTER * HIDDEN) / 4; i += 256)
                ((float4*)ws)[i] = src[i];
        }
        __syncthreads();   // ws (and, on d=0, us/hs) visible
        #pragma unroll
        for (int j = 0; j < INTER; j++) {
            float w = ws[j * HIDDEN + hid];                       // conflict-free
            acc0 = fmaf(us[b0 * USTRIDE + d * INTER + j],       w, acc0);
            acc1 = fmaf(us[(b0 + 2) * USTRIDE + d * INTER + j], w, acc1);
        }
        __syncthreads();   // protect ws before next overwrite
    }

    // hidden path: Hw streamed in two 64-row halves through ws
    for (int half = 0; half < 2; half++) {
        {
            const float4* src = (const float4*)(hw + (size_t)half * 64 * HIDDEN);
            #pragma unroll 4
            for (int i = t; i < (64 * HIDDEN) / 4; i += 256)
                ((float4*)ws)[i] = src[i];
        }
        __syncthreads();
        #pragma unroll
        for (int j = 0; j < 64; j++) {
            float w = ws[j * HIDDEN + hid];
            int k = half * 64 + j;
            acc0 = fmaf(hs[b0 * HIDDEN + k],       w, acc0);
            acc1 = fmaf(hs[(b0 + 2) * HIDDEN + k], w, acc1);
        }
        __syncthreads();
    }

    out[(size_t)(bbase + b0)     * HIDDEN + hid] = 1.f / (1.f + expf(-acc0));
    out[(size_t)(bbase + b0 + 2) * HIDDEN + hid] = 1.f / (1.f + expf(-acc1));
}

// ---------------------------------------------------------------------------
// kernel_launch: two stream-ordered launches (graph-capturable, alloc-free)
// ---------------------------------------------------------------------------
extern "C" void kernel_launch(void* const* d_in, const int* in_sizes, int n_in,
                              void* d_out, int out_size) {
    const float* x    = (const float*)d_in[0];
    const int*   tc   = (const int*)d_in[1];
    const int*   dc   = (const int*)d_in[2];
    const int*   mask = (const int*)d_in[3];
    const float* h    = (const float*)d_in[4];
    const float* tw   = (const float*)d_in[5];
    const float* dw   = (const float*)d_in[6];
    const float* hw   = (const float*)d_in[7];
    float*       out  = (float*)d_out;

    stage1_kernel<<<dim3(NSLOT, GRIDY), 256>>>(x, tc, dc, mask, tw);
    stage2_kernel<<<64, 256>>>(h, dw, hw, out);
}

// round 6
// speedup vs baseline: 1.6205x; 1.0624x over previous
#include <cuda_runtime.h>
#include <math.h>

#define NROWS   12800     // B*C
#define BATCH   256
#define CDIM    50
#define INPUT   128
#define INTER   64
#define HIDDEN  128
#define NSLOT   11
#define USTRIDE (NSLOT * INTER)   // 704
#define GRIDY   64
#define RPC     (NROWS / GRIDY)   // 200 rows per chunk
#define KDIM    (USTRIDE + HIDDEN)   // 832 = 13 rounds of 64
#define NROUND  (KDIM / 64)          // 13

// Bucketed accumulator u[b][dist_slot][j], fp32. Zero-initialized at module
// load; stage2 re-zeroes it after consuming, so every launch (and every graph
// replay) starts from zeros without a dedicated zeroing kernel.
__device__ float g_u[BATCH * USTRIDE];

// ---------------------------------------------------------------------------
// K1: slot-major stage 1 with in-CTA compaction + 2-row pairing. (unchanged)
// ---------------------------------------------------------------------------
__global__ __launch_bounds__(256) void stage1_kernel(
    const float* __restrict__ x,          // (B,C,INPUT)
    const int* __restrict__ tc,           // (B,C)
    const int* __restrict__ dc,           // (B,C)
    const int* __restrict__ mask,         // (B,C) bool promoted to int32
    const float* __restrict__ tw)         // (NSLOT, INPUT, INTER)
{
    __shared__ float tws[INPUT * INTER];  // 32 KB
    __shared__ int   list[RPC];
    __shared__ int   cnt;

    const int s   = blockIdx.x;
    const int r0  = blockIdx.y * RPC;
    const int tid = threadIdx.x;

    if (tid == 0) cnt = 0;

    {
        const float4* src = (const float4*)(tw + (size_t)s * INPUT * INTER);
        #pragma unroll 4
        for (int i = tid; i < (INPUT * INTER) / 4; i += 256)
            ((float4*)tws)[i] = src[i];
    }
    __syncthreads();

    if (tid < RPC) {
        int r = r0 + tid;
        if (tc[r] == s && mask[r] != 0) {
            int pos = atomicAdd(&cnt, 1);
            list[pos] = (dc[r] << 16) | r;
        }
    }
    __syncthreads();

    const int n    = cnt;
    const int warp = tid >> 5;
    const int lane = tid & 31;
    const int j0   = lane * 2;

    for (int i = warp * 2; i < n; i += 16) {
        const int  e0   = list[i];
        const bool has2 = (i + 1) < n;
        const int  e1   = has2 ? list[i + 1] : e0;
        const int  ra   = e0 & 0xFFFF, da = e0 >> 16;
        const int  rb   = e1 & 0xFFFF, db = e1 >> 16;
        const float* xa = x + (size_t)ra * INPUT;
        const float* xb = x + (size_t)rb * INPUT;

        float a0 = 0.f, a1 = 0.f, b0 = 0.f, b1 = 0.f;
        #pragma unroll 8
        for (int k = 0; k < INPUT; k += 4) {
            float4 va = *(const float4*)(xa + k);
            float4 vb = *(const float4*)(xb + k);
            float2 w0 = *(const float2*)(tws + (k + 0) * INTER + j0);
            float2 w1 = *(const float2*)(tws + (k + 1) * INTER + j0);
            float2 w2 = *(const float2*)(tws + (k + 2) * INTER + j0);
            float2 w3 = *(const float2*)(tws + (k + 3) * INTER + j0);
            a0 = fmaf(va.x, w0.x, a0);  a1 = fmaf(va.x, w0.y, a1);
            b0 = fmaf(vb.x, w0.x, b0);  b1 = fmaf(vb.x, w0.y, b1);
            a0 = fmaf(va.y, w1.x, a0);  a1 = fmaf(va.y, w1.y, a1);
            b0 = fmaf(vb.y, w1.x, b0);  b1 = fmaf(vb.y, w1.y, b1);
            a0 = fmaf(va.z, w2.x, a0);  a1 = fmaf(va.z, w2.y, a1);
            b0 = fmaf(vb.z, w2.x, b0);  b1 = fmaf(vb.z, w2.y, b1);
            a0 = fmaf(va.w, w3.x, a0);  a1 = fmaf(va.w, w3.y, a1);
            b0 = fmaf(vb.w, w3.x, b0);  b1 = fmaf(vb.w, w3.y, b1);
        }

        float* ua = g_u + (size_t)(ra / CDIM) * USTRIDE + da * INTER + j0;
        atomicAdd(ua,     a0);
        atomicAdd(ua + 1, a1);
        if (has2) {
            float* ub = g_u + (size_t)(rb / CDIM) * USTRIDE + db * INTER + j0;
            atomicAdd(ub,     b0);
            atomicAdd(ub + 1, b1);
        }
    }
}

// ---------------------------------------------------------------------------
// K2: GEMM view: out[4,128] = sigmoid(A[4,832] @ W[832,128]) per CTA, where
// A = [u | h] in smem, W rounds (11 dw slices + 2 hw halves) streamed through
// one 32 KB smem buffer with register-staged prefetch (GMEM load of round
// r+1 overlaps compute of round r). Includes read-then-rezero of g_u.
// ---------------------------------------------------------------------------
__global__ __launch_bounds__(256) void stage2_kernel(
    const float* __restrict__ h,    // (B, HIDDEN)
    const float* __restrict__ dw,   // (NSLOT, INTER, HIDDEN)
    const float* __restrict__ hw,   // (HIDDEN, HIDDEN)
    float* __restrict__ out)        // (B, HIDDEN)
{
    __shared__ float ws[64 * HIDDEN];   // 32 KB: current W round (64 x 128)
    __shared__ float as[4 * KDIM];      // 13.3 KB: A = [u | h] for 4 batches

    const int t     = threadIdx.x;
    const int bbase = blockIdx.x * 4;
    const int b0    = t >> 7;     // 0..1
    const int hid   = t & 127;

    // Build A: load u slice (and rezero g_u — each element touched by exactly
    // one thread), then append h.
    {
        float4* gu4 = (float4*)(g_u + (size_t)bbase * USTRIDE);
        float4* as4 = (float4*)as;
        const float4 z = make_float4(0.f, 0.f, 0.f, 0.f);
        #pragma unroll
        for (int i = t; i < 4 * USTRIDE / 4; i += 256) {   // 704 float4
            int bl = i / (USTRIDE / 4);                    // /176
            int rm = i % (USTRIDE / 4);
            float4 v = gu4[i];
            as4[bl * (KDIM / 4) + rm] = v;                 // *208
            gu4[i] = z;
        }
        const float4* h4 = (const float4*)(h + (size_t)bbase * HIDDEN);
        for (int i = t; i < 4 * HIDDEN / 4; i += 256) {    // 128 float4
            int bl = i / (HIDDEN / 4);                     // /32
            int rm = i % (HIDDEN / 4);
            as4[bl * (KDIM / 4) + (USTRIDE / 4) + rm] = h4[i];
        }
    }

    // Prefetch round 0 of W into registers.
    float4 pf[8];
    {
        const float4* src = (const float4*)dw;
        #pragma unroll
        for (int i = 0; i < 8; i++) pf[i] = src[t + i * 256];
    }

    float acc0 = 0.f, acc1 = 0.f;
    const float* arow0 = as + b0 * KDIM;
    const float* arow1 = as + (b0 + 2) * KDIM;

    for (int r = 0; r < NROUND; r++) {
        __syncthreads();   // prior round's compute done (and round 0: as ready)
        {
            float4* ws4 = (float4*)ws;
            #pragma unroll
            for (int i = 0; i < 8; i++) ws4[t + i * 256] = pf[i];
        }
        if (r + 1 < NROUND) {   // issue next round's loads; in flight during compute
            const float* nsrc = (r + 1 < NSLOT)
                ? dw + (size_t)(r + 1) * 64 * HIDDEN
                : hw + (size_t)(r + 1 - NSLOT) * 64 * HIDDEN;
            const float4* src = (const float4*)nsrc;
            #pragma unroll
            for (int i = 0; i < 8; i++) pf[i] = src[t + i * 256];
        }
        __syncthreads();   // ws ready

        const int kbase = r * 64;
        #pragma unroll
        for (int j = 0; j < 64; j += 4) {
            float4 a0 = *(const float4*)(arow0 + kbase + j);   // broadcast
            float4 a1 = *(const float4*)(arow1 + kbase + j);
            float w0 = ws[(j + 0) * HIDDEN + hid];             // conflict-free
            float w1 = ws[(j + 1) * HIDDEN + hid];
            float w2 = ws[(j + 2) * HIDDEN + hid];
            float w3 = ws[(j + 3) * HIDDEN + hid];
            acc0 = fmaf(a0.x, w0, acc0);  acc1 = fmaf(a1.x, w0, acc1);
            acc0 = fmaf(a0.y, w1, acc0);  acc1 = fmaf(a1.y, w1, acc1);
            acc0 = fmaf(a0.z, w2, acc0);  acc1 = fmaf(a1.z, w2, acc1);
            acc0 = fmaf(a0.w, w3, acc0);  acc1 = fmaf(a1.w, w3, acc1);
        }
    }

    out[(size_t)(bbase + b0)     * HIDDEN + hid] = 1.f / (1.f + expf(-acc0));
    out[(size_t)(bbase + b0 + 2) * HIDDEN + hid] = 1.f / (1.f + expf(-acc1));
}

// ---------------------------------------------------------------------------
// kernel_launch: two stream-ordered launches (graph-capturable, alloc-free)
// ---------------------------------------------------------------------------
extern "C" void kernel_launch(void* const* d_in, const int* in_sizes, int n_in,
                              void* d_out, int out_size) {
    const float* x    = (const float*)d_in[0];
    const int*   tc   = (const int*)d_in[1];
    const int*   dc   = (const int*)d_in[2];
    const int*   mask = (const int*)d_in[3];
    const float* h    = (const float*)d_in[4];
    const float* tw   = (const float*)d_in[5];
    const float* dw   = (const float*)d_in[6];
    const float* hw   = (const float*)d_in[7];
    float*       out  = (float*)d_out;

    stage1_kernel<<<dim3(NSLOT, GRIDY), 256>>>(x, tc, dc, mask, tw);
    stage2_kernel<<<64, 256>>>(h, dw, hw, out);
}

// round 7
// speedup vs baseline: 1.8293x; 1.1289x over previous
#include <cuda_runtime.h>
#include <math.h>

#define NROWS   12800     // B*C
#define BATCH   256
#define CDIM    50
#define INPUT   128
#define INTER   64
#define HIDDEN  128
#define NSLOT   11
#define USTRIDE (NSLOT * INTER)      // 704
#define GRIDY   32
#define RPC     (NROWS / GRIDY)      // 400 rows per chunk
#define KDIM    (USTRIDE + HIDDEN)   // 832 = 13 rounds of 64
#define NROUND  (KDIM / 64)          // 13

// Bucketed accumulator u[b][dist_slot][j]. Zero-init at load; the stage2 CTA
// that consumes each slot rezeroes it -> replay-safe without a zero kernel.
__device__ float g_u[BATCH * USTRIDE];
// Pre-sigmoid output accumulator (K-split partials). Zero-init; finisher
// rezeroes after reading.
__device__ float g_acc[BATCH * HIDDEN];
// Monotonic finisher counters (never reset; (r & 3) == 3 fires exactly once
// per bx per launch, every launch/replay).
__device__ unsigned g_cnt[64];

// ---------------------------------------------------------------------------
// K1: slot-major stage 1 with in-CTA compaction + 2-row pairing.
// grid = (11 slots, 32 chunks of 400 rows) = 352 CTAs.
// ---------------------------------------------------------------------------
__global__ __launch_bounds__(256) void stage1_kernel(
    const float* __restrict__ x,          // (B,C,INPUT)
    const int* __restrict__ tc,           // (B,C)
    const int* __restrict__ dc,           // (B,C)
    const int* __restrict__ mask,         // (B,C) bool promoted to int32
    const float* __restrict__ tw)         // (NSLOT, INPUT, INTER)
{
    __shared__ float tws[INPUT * INTER];  // 32 KB
    __shared__ int   list[RPC];
    __shared__ int   cnt;

    const int s   = blockIdx.x;
    const int r0  = blockIdx.y * RPC;
    const int tid = threadIdx.x;

    if (tid == 0) cnt = 0;

    {
        const float4* src = (const float4*)(tw + (size_t)s * INPUT * INTER);
        #pragma unroll 4
        for (int i = tid; i < (INPUT * INTER) / 4; i += 256)
            ((float4*)tws)[i] = src[i];
    }
    __syncthreads();

    for (int i = tid; i < RPC; i += 256) {
        int r = r0 + i;
        if (tc[r] == s && mask[r] != 0) {
            int pos = atomicAdd(&cnt, 1);
            list[pos] = (dc[r] << 16) | r;
        }
    }
    __syncthreads();

    const int n    = cnt;
    const int warp = tid >> 5;
    const int lane = tid & 31;
    const int j0   = lane * 2;

    for (int i = warp * 2; i < n; i += 16) {
        const int  e0   = list[i];
        const bool has2 = (i + 1) < n;
        const int  e1   = has2 ? list[i + 1] : e0;
        const int  ra   = e0 & 0xFFFF, da = e0 >> 16;
        const int  rb   = e1 & 0xFFFF, db = e1 >> 16;
        const float* xa = x + (size_t)ra * INPUT;
        const float* xb = x + (size_t)rb * INPUT;

        float a0 = 0.f, a1 = 0.f, b0 = 0.f, b1 = 0.f;
        #pragma unroll 8
        for (int k = 0; k < INPUT; k += 4) {
            float4 va = *(const float4*)(xa + k);   // broadcast across warp
            float4 vb = *(const float4*)(xb + k);
            float2 w0 = *(const float2*)(tws + (k + 0) * INTER + j0);
            float2 w1 = *(const float2*)(tws + (k + 1) * INTER + j0);
            float2 w2 = *(const float2*)(tws + (k + 2) * INTER + j0);
            float2 w3 = *(const float2*)(tws + (k + 3) * INTER + j0);
            a0 = fmaf(va.x, w0.x, a0);  a1 = fmaf(va.x, w0.y, a1);
            b0 = fmaf(vb.x, w0.x, b0);  b1 = fmaf(vb.x, w0.y, b1);
            a0 = fmaf(va.y, w1.x, a0);  a1 = fmaf(va.y, w1.y, a1);
            b0 = fmaf(vb.y, w1.x, b0);  b1 = fmaf(vb.y, w1.y, b1);
            a0 = fmaf(va.z, w2.x, a0);  a1 = fmaf(va.z, w2.y, a1);
            b0 = fmaf(vb.z, w2.x, b0);  b1 = fmaf(vb.z, w2.y, b1);
            a0 = fmaf(va.w, w3.x, a0);  a1 = fmaf(va.w, w3.y, a1);
            b0 = fmaf(vb.w, w3.x, b0);  b1 = fmaf(vb.w, w3.y, b1);
        }

        float* ua = g_u + (size_t)(ra / CDIM) * USTRIDE + da * INTER + j0;
        atomicAdd(ua,     a0);
        atomicAdd(ua + 1, a1);
        if (has2) {
            float* ub = g_u + (size_t)(rb / CDIM) * USTRIDE + db * INTER + j0;
            atomicAdd(ub,     b0);
            atomicAdd(ub + 1, b1);
        }
    }
}

// ---------------------------------------------------------------------------
// K2: K-split GEMM  out[4,128] = sigmoid(A[4,832] @ W[832,128]) per bx.
// grid = (64 bx, 4 kc). CTA (bx,kc) computes rounds {kc, kc+4, kc+8, kc+12},
// atomicAdds partials into g_acc; the 4th-arriving CTA per bx (monotonic
// counter) applies sigmoid + writes out + rezeroes g_acc.
// Each u slot is read+rezeroed by exactly one CTA.
// ---------------------------------------------------------------------------
__global__ __launch_bounds__(256) void stage2_kernel(
    const float* __restrict__ h,    // (B, HIDDEN)
    const float* __restrict__ dw,   // (NSLOT, INTER, HIDDEN)
    const float* __restrict__ hw,   // (HIDDEN, HIDDEN)
    float* __restrict__ out)        // (B, HIDDEN)
{
    __shared__ float ws[64 * HIDDEN];   // 32 KB: current W round
    __shared__ float as[4 * 4 * 64];    // 4 KB: A slice [round][batch][64]
    __shared__ int   flag;

    const int t     = threadIdx.x;
    const int bx    = blockIdx.x;       // 0..63
    const int kc    = blockIdx.y;       // 0..3
    const int bbase = bx * 4;
    const int nr    = 3 + (kc == 0);    // rounds this CTA owns
    const int b0    = t >> 7;           // 0..1
    const int hid   = t & 127;

    // Load A slice (u slots: read + rezero; h halves: read only).
    {
        const int bb = t >> 6, j = t & 63;   // t = bb*64 + j
        #pragma unroll
        for (int li = 0; li < 4; li++) {
            if (li >= nr) break;
            const int r = kc + 4 * li;
            float v;
            if (r < NSLOT) {
                float* up = g_u + (size_t)(bbase + bb) * USTRIDE + r * 64 + j;
                v = *up;
                *up = 0.f;
            } else {
                v = h[(size_t)(bbase + bb) * HIDDEN + (r - NSLOT) * 64 + j];
            }
            as[li * 256 + t] = v;
        }
    }

    // Prefetch first round's W into registers.
    float4 pf[8];
    {
        const float* s0 = (kc < NSLOT) ? dw + (size_t)kc * 64 * HIDDEN
                                       : hw + (size_t)(kc - NSLOT) * 64 * HIDDEN;
        const float4* src = (const float4*)s0;
        #pragma unroll
        for (int i = 0; i < 8; i++) pf[i] = src[t + i * 256];
    }

    float acc0 = 0.f, acc1 = 0.f;

    for (int li = 0; li < nr; li++) {
        __syncthreads();   // previous round's readers done (li=0: as ready)
        {
            float4* ws4 = (float4*)ws;
            #pragma unroll
            for (int i = 0; i < 8; i++) ws4[t + i * 256] = pf[i];
        }
        if (li + 1 < nr) {
            const int rn = kc + 4 * (li + 1);
            const float* sn = (rn < NSLOT) ? dw + (size_t)rn * 64 * HIDDEN
                                           : hw + (size_t)(rn - NSLOT) * 64 * HIDDEN;
            const float4* src = (const float4*)sn;
            #pragma unroll
            for (int i = 0; i < 8; i++) pf[i] = src[t + i * 256];
        }
        __syncthreads();   // ws ready

        const float* a0p = as + li * 256 + b0 * 64;
        const float* a1p = as + li * 256 + (b0 + 2) * 64;
        #pragma unroll
        for (int j = 0; j < 64; j += 4) {
            float4 a0 = *(const float4*)(a0p + j);   // broadcast
            float4 a1 = *(const float4*)(a1p + j);
            float w0 = ws[(j + 0) * HIDDEN + hid];   // conflict-free
            float w1 = ws[(j + 1) * HIDDEN + hid];
            float w2 = ws[(j + 2) * HIDDEN + hid];
            float w3 = ws[(j + 3) * HIDDEN + hid];
            acc0 = fmaf(a0.x, w0, acc0);  acc1 = fmaf(a1.x, w0, acc1);
            acc0 = fmaf(a0.y, w1, acc0);  acc1 = fmaf(a1.y, w1, acc1);
            acc0 = fmaf(a0.z, w2, acc0);  acc1 = fmaf(a1.z, w2, acc1);
            acc0 = fmaf(a0.w, w3, acc0);  acc1 = fmaf(a1.w, w3, acc1);
        }
    }

    // Deposit partials.
    float* p0 = g_acc + (size_t)(bbase + b0) * HIDDEN + hid;
    float* p1 = g_acc + (size_t)(bbase + b0 + 2) * HIDDEN + hid;
    atomicAdd(p0, acc0);
    atomicAdd(p1, acc1);

    // Finisher election: 4th-arriving CTA for this bx.
    __threadfence();
    __syncthreads();
    if (t == 0) {
        unsigned r = atomicAdd(&g_cnt[bx], 1u);
        flag = ((r & 3u) == 3u) ? 1 : 0;
    }
    __syncthreads();

    if (flag) {
        float v0 = __ldcg(p0);
        float v1 = __ldcg(p1);
        out[(size_t)(bbase + b0)     * HIDDEN + hid] = 1.f / (1.f + expf(-v0));
        out[(size_t)(bbase + b0 + 2) * HIDDEN + hid] = 1.f / (1.f + expf(-v1));
        *p0 = 0.f;   // rezero for next launch/replay
        *p1 = 0.f;
    }
}

// ---------------------------------------------------------------------------
// kernel_launch: two stream-ordered launches (graph-capturable, alloc-free)
// ---------------------------------------------------------------------------
extern "C" void kernel_launch(void* const* d_in, const int* in_sizes, int n_in,
                              void* d_out, int out_size) {
    const float* x    = (const float*)d_in[0];
    const int*   tc   = (const int*)d_in[1];
    const int*   dc   = (const int*)d_in[2];
    const int*   mask = (const int*)d_in[3];
    const float* h    = (const float*)d_in[4];
    const float* tw   = (const float*)d_in[5];
    const float* dw   = (const float*)d_in[6];
    const float* hw   = (const float*)d_in[7];
    float*       out  = (float*)d_out;

    stage1_kernel<<<dim3(NSLOT, GRIDY), 256>>>(x, tc, dc, mask, tw);
    stage2_kernel<<<dim3(64, 4), 256>>>(h, dw, hw, out);
}

// round 8
// speedup vs baseline: 1.9964x; 1.0913x over previous
#include <cuda_runtime.h>
#include <math.h>

#define NROWS   12800     // B*C
#define BATCH   256
#define CDIM    50
#define INPUT   128
#define INTER   64
#define HIDDEN  128
#define NSLOT   11
#define USTRIDE (NSLOT * INTER)      // 704
#define GRIDY   32
#define RPC     (NROWS / GRIDY)      // 400 rows per chunk
#define NROUND  13                   // 11 dw slots + 2 hw halves
#define BPG     8                    // batches per stage2 CTA

// Bucketed accumulator u[b][dist_slot][j]. Zero-init at load; the stage2 CTA
// that consumes each slot rezeroes it -> replay-safe without a zero kernel.
__device__ float g_u[BATCH * USTRIDE];
// Pre-sigmoid output accumulator. Zero-init; finisher rezeroes after reading.
__device__ float g_acc[BATCH * HIDDEN];
// Monotonic finisher counters (never reset; (c % 13) == 12 fires exactly once
// per bx per launch, every launch/replay).
__device__ unsigned g_cnt[32];

// ---------------------------------------------------------------------------
// K1: slot-major stage 1 with in-CTA compaction + 2-row pairing. (unchanged)
// grid = (11 slots, 32 chunks of 400 rows) = 352 CTAs.
// ---------------------------------------------------------------------------
__global__ __launch_bounds__(256) void stage1_kernel(
    const float* __restrict__ x,          // (B,C,INPUT)
    const int* __restrict__ tc,           // (B,C)
    const int* __restrict__ dc,           // (B,C)
    const int* __restrict__ mask,         // (B,C) bool promoted to int32
    const float* __restrict__ tw)         // (NSLOT, INPUT, INTER)
{
    __shared__ float tws[INPUT * INTER];  // 32 KB
    __shared__ int   list[RPC];
    __shared__ int   cnt;

    const int s   = blockIdx.x;
    const int r0  = blockIdx.y * RPC;
    const int tid = threadIdx.x;

    if (tid == 0) cnt = 0;

    {
        const float4* src = (const float4*)(tw + (size_t)s * INPUT * INTER);
        #pragma unroll 4
        for (int i = tid; i < (INPUT * INTER) / 4; i += 256)
            ((float4*)tws)[i] = src[i];
    }
    __syncthreads();

    for (int i = tid; i < RPC; i += 256) {
        int r = r0 + i;
        if (tc[r] == s && mask[r] != 0) {
            int pos = atomicAdd(&cnt, 1);
            list[pos] = (dc[r] << 16) | r;
        }
    }
    __syncthreads();

    const int n    = cnt;
    const int warp = tid >> 5;
    const int lane = tid & 31;
    const int j0   = lane * 2;

    for (int i = warp * 2; i < n; i += 16) {
        const int  e0   = list[i];
        const bool has2 = (i + 1) < n;
        const int  e1   = has2 ? list[i + 1] : e0;
        const int  ra   = e0 & 0xFFFF, da = e0 >> 16;
        const int  rb   = e1 & 0xFFFF, db = e1 >> 16;
        const float* xa = x + (size_t)ra * INPUT;
        const float* xb = x + (size_t)rb * INPUT;

        float a0 = 0.f, a1 = 0.f, b0 = 0.f, b1 = 0.f;
        #pragma unroll 8
        for (int k = 0; k < INPUT; k += 4) {
            float4 va = *(const float4*)(xa + k);   // broadcast across warp
            float4 vb = *(const float4*)(xb + k);
            float2 w0 = *(const float2*)(tws + (k + 0) * INTER + j0);
            float2 w1 = *(const float2*)(tws + (k + 1) * INTER + j0);
            float2 w2 = *(const float2*)(tws + (k + 2) * INTER + j0);
            float2 w3 = *(const float2*)(tws + (k + 3) * INTER + j0);
            a0 = fmaf(va.x, w0.x, a0);  a1 = fmaf(va.x, w0.y, a1);
            b0 = fmaf(vb.x, w0.x, b0);  b1 = fmaf(vb.x, w0.y, b1);
            a0 = fmaf(va.y, w1.x, a0);  a1 = fmaf(va.y, w1.y, a1);
            b0 = fmaf(vb.y, w1.x, b0);  b1 = fmaf(vb.y, w1.y, b1);
            a0 = fmaf(va.z, w2.x, a0);  a1 = fmaf(va.z, w2.y, a1);
            b0 = fmaf(vb.z, w2.x, b0);  b1 = fmaf(vb.z, w2.y, b1);
            a0 = fmaf(va.w, w3.x, a0);  a1 = fmaf(va.w, w3.y, a1);
            b0 = fmaf(vb.w, w3.x, b0);  b1 = fmaf(vb.w, w3.y, b1);
        }

        float* ua = g_u + (size_t)(ra / CDIM) * USTRIDE + da * INTER + j0;
        atomicAdd(ua,     a0);
        atomicAdd(ua + 1, a1);
        if (has2) {
            float* ub = g_u + (size_t)(rb / CDIM) * USTRIDE + db * INTER + j0;
            atomicAdd(ub,     b0);
            atomicAdd(ub + 1, b1);
        }
    }
}

// ---------------------------------------------------------------------------
// K2: FLAT K-split GEMM. grid = (32 bx, 13 rounds); CTA (bx, r) computes the
// contribution of k-range [r*64, r*64+64) for 8 batches in ONE pass:
// no round loop, no serial chain. Partials atomicAdd into g_acc; the 13th
// arriving CTA per bx (monotonic counter) applies sigmoid + writes out +
// rezeroes g_acc. Rounds 0..10 read+rezero their g_u slot (exactly one CTA
// per (batch-group, slot)); rounds 11..12 read h.
// ---------------------------------------------------------------------------
__global__ __launch_bounds__(256) void stage2_kernel(
    const float* __restrict__ h,    // (B, HIDDEN)
    const float* __restrict__ dw,   // (NSLOT, INTER, HIDDEN)
    const float* __restrict__ hw,   // (HIDDEN, HIDDEN)
    float* __restrict__ out)        // (B, HIDDEN)
{
    __shared__ float ws[64 * HIDDEN];   // 32 KB: this round's W slice
    __shared__ float as[BPG * 64];      // 2 KB: A slice for 8 batches
    __shared__ int   flag;

    const int t     = threadIdx.x;
    const int bx    = blockIdx.x;       // 0..31
    const int r     = blockIdx.y;       // 0..12
    const int bbase = bx * BPG;
    const int bg    = t >> 7;           // 0..1
    const int hid   = t & 127;

    // Load W round (8 float4/thread) — issued first so it's in flight while
    // the A slice loads below also stream.
    {
        const float* wsrc = (r < NSLOT)
            ? dw + (size_t)r * 64 * HIDDEN
            : hw + (size_t)(r - NSLOT) * 64 * HIDDEN;
        const float4* src = (const float4*)wsrc;
        float4* ws4 = (float4*)ws;
        #pragma unroll
        for (int i = 0; i < 8; i++) ws4[t + i * 256] = src[t + i * 256];
    }

    // Load A slice: 8 batches x 64 k = 512 floats, 2 per thread.
    // u rounds: read + rezero (each (b, slot) element touched exactly once).
    #pragma unroll
    for (int i = 0; i < 2; i++) {
        int idx = t + i * 256;            // 0..511
        int bb = idx >> 6, j = idx & 63;
        float v;
        if (r < NSLOT) {
            float* up = g_u + (size_t)(bbase + bb) * USTRIDE + r * 64 + j;
            v = *up;
            *up = 0.f;
        } else {
            v = h[(size_t)(bbase + bb) * HIDDEN + (r - NSLOT) * 64 + j];
        }
        as[idx] = v;
    }
    __syncthreads();

    // Compute: 4 batches per thread (bg, bg+2, bg+4, bg+6), 64 k-steps.
    float acc0 = 0.f, acc1 = 0.f, acc2 = 0.f, acc3 = 0.f;
    #pragma unroll
    for (int j = 0; j < 64; j += 4) {
        float w0 = ws[(j + 0) * HIDDEN + hid];   // conflict-free
        float w1 = ws[(j + 1) * HIDDEN + hid];
        float w2 = ws[(j + 2) * HIDDEN + hid];
        float w3 = ws[(j + 3) * HIDDEN + hid];
        float4 a0 = *(const float4*)(as + (bg + 0) * 64 + j);   // broadcast
        float4 a1 = *(const float4*)(as + (bg + 2) * 64 + j);
        float4 a2 = *(const float4*)(as + (bg + 4) * 64 + j);
        float4 a3 = *(const float4*)(as + (bg + 6) * 64 + j);
        acc0 = fmaf(a0.x, w0, acc0);  acc1 = fmaf(a1.x, w0, acc1);
        acc2 = fmaf(a2.x, w0, acc2);  acc3 = fmaf(a3.x, w0, acc3);
        acc0 = fmaf(a0.y, w1, acc0);  acc1 = fmaf(a1.y, w1, acc1);
        acc2 = fmaf(a2.y, w1, acc2);  acc3 = fmaf(a3.y, w1, acc3);
        acc0 = fmaf(a0.z, w2, acc0);  acc1 = fmaf(a1.z, w2, acc1);
        acc2 = fmaf(a2.z, w2, acc2);  acc3 = fmaf(a3.z, w2, acc3);
        acc0 = fmaf(a0.w, w3, acc0);  acc1 = fmaf(a1.w, w3, acc1);
        acc2 = fmaf(a2.w, w3, acc2);  acc3 = fmaf(a3.w, w3, acc3);
    }

    // Deposit partials (spread addresses -> REDG-class throughput).
    atomicAdd(g_acc + (size_t)(bbase + bg + 0) * HIDDEN + hid, acc0);
    atomicAdd(g_acc + (size_t)(bbase + bg + 2) * HIDDEN + hid, acc1);
    atomicAdd(g_acc + (size_t)(bbase + bg + 4) * HIDDEN + hid, acc2);
    atomicAdd(g_acc + (size_t)(bbase + bg + 6) * HIDDEN + hid, acc3);

    // Finisher election: 13th-arriving CTA for this bx.
    __threadfence();
    __syncthreads();
    if (t == 0) {
        unsigned c = atomicAdd(&g_cnt[bx], 1u);
        flag = ((c % 13u) == 12u) ? 1 : 0;
    }
    __syncthreads();

    if (flag) {
        #pragma unroll
        for (int i = 0; i < 4; i++) {
            float* p = g_acc + (size_t)(bbase + bg + 2 * i) * HIDDEN + hid;
            float v = __ldcg(p);
            out[(size_t)(bbase + bg + 2 * i) * HIDDEN + hid] =
                1.f / (1.f + expf(-v));
            *p = 0.f;   // rezero for next launch/replay
        }
    }
}

// ---------------------------------------------------------------------------
// kernel_launch: two stream-ordered launches (graph-capturable, alloc-free)
// ---------------------------------------------------------------------------
extern "C" void kernel_launch(void* const* d_in, const int* in_sizes, int n_in,
                              void* d_out, int out_size) {
    const float* x    = (const float*)d_in[0];
    const int*   tc   = (const int*)d_in[1];
    const int*   dc   = (const int*)d_in[2];
    const int*   mask = (const int*)d_in[3];
    const float* h    = (const float*)d_in[4];
    const float* tw   = (const float*)d_in[5];
    const float* dw   = (const float*)d_in[6];
    const float* hw   = (const float*)d_in[7];
    float*       out  = (float*)d_out;

    stage1_kernel<<<dim3(NSLOT, GRIDY), 256>>>(x, tc, dc, mask, tw);
    stage2_kernel<<<dim3(32, NROUND), 256>>>(h, dw, hw, out);
}